// round 16
// baseline (speedup 1.0000x reference)
#include <cuda_runtime.h>
#include <stdint.h>

// SGC 2-hop: out = S^2 x W^T + b,  S = D^-1/2 (A + I) D^-1/2
// Identity: (S^2 x) W^T == S^2 (x W^T) -> project to scalar FIRST.
// R15: fused project+count becomes a single-wave (148x4 blocks) grid-stride
// persistent kernel -> no tail-wave imbalance on the DRAM-bound stream.
// Scatters untouched (measured L1tex wavefront floor ~9.5us each).

#define MAXN  100000
#define DFEAT 128
#define PROWS 8          // rows per warp in projection (measured best)
#define PC_BLOCKS 592    // 148 SMs * 4 blocks — always a single resident wave
#define PC_T      256

__device__ int   g_cnt[MAXN];   // in-degree (excl. self loop)
__device__ float g_y[MAXN];     // raw projection x @ W^T
__device__ float g_dis[MAXN];   // deg^-1/2
__device__ float g_z[MAXN];     // scalar being propagated
__device__ float g_acc[MAXN];   // scatter accumulator
__device__ int   g_is32;        // zero-init at load; sticky (set-to-1 only)

__device__ __forceinline__ int load_idx(const void* ei, int is32, long long pos) {
    if (is32) return __ldg((const int*)ei + pos);
    return (int)__ldg((const long long*)ei + pos);
}

// ---- kernel 0: zero counts; first 2048 threads detect index dtype on a
// 4096-word prefix (int64 LE < 2^31 => odd words all zero; random int32
// indices defeat this with P ~ 1-1e-5 per word). Sticky => deterministic.
__global__ void k_init_detect(const int* __restrict__ w, int e, int n) {
    int i = blockIdx.x * blockDim.x + threadIdx.x;
    if (i < n) g_cnt[i] = 0;
    if (i < 2048) {
        long long lim = 2LL * e;
        long long p = 2LL * i + 1;
        if (p < lim && __ldg(w + p) != 0) g_is32 = 1;
    }
}

// ---- kernel 1 (fused, persistent single wave):
//   phase A (warp-stride): y = x @ W^T, 8 rows/warp, MLP=8
//   phase B (thread-stride): in-degree count over col
// No inter-block dependency: outputs g_y and g_cnt consumed only by k_prep.
__global__ void __launch_bounds__(PC_T)
k_project_count(const float* __restrict__ x,
                const float* __restrict__ W,
                const void* __restrict__ ei,
                int n, int e) {
    int lane = threadIdx.x & 31;
    int warp_gid = (blockIdx.x * blockDim.x + threadIdx.x) >> 5;
    int nwarps = (gridDim.x * blockDim.x) >> 5;
    int ngroups = (n + PROWS - 1) / PROWS;

    float4 w = reinterpret_cast<const float4*>(W)[lane];

    for (int g = warp_gid; g < ngroups; g += nwarps) {
        int base = g * PROWS;
        int rows = n - base; if (rows > PROWS) rows = PROWS;

        const float4* xv = reinterpret_cast<const float4*>(x)
                           + (size_t)base * (DFEAT / 4) + lane;
        float4 a[PROWS];
        #pragma unroll
        for (int j = 0; j < PROWS; j++)
            if (j < rows) a[j] = xv[(size_t)j * (DFEAT / 4)];

        #pragma unroll
        for (int j = 0; j < PROWS; j++) {
            if (j >= rows) break;
            float d = a[j].x * w.x + a[j].y * w.y + a[j].z * w.z + a[j].w * w.w;
            #pragma unroll
            for (int off = 16; off > 0; off >>= 1)
                d += __shfl_down_sync(0xFFFFFFFFu, d, off);
            if (lane == 0) g_y[base + j] = d;
        }
    }

    // phase B: degree count (thread grid-stride, coalesced index reads)
    int tid = blockIdx.x * blockDim.x + threadIdx.x;
    int nthreads = gridDim.x * blockDim.x;
    int is32 = g_is32;
    for (int i = tid; i < e; i += nthreads) {
        int c = load_idx(ei, is32, (long long)e + i);
        if ((unsigned)c < (unsigned)n) atomicAdd(&g_cnt[c], 1);
    }
}

// ---- kernel 2: dis = rsqrt(deg); z = dis*y; acc = z (self loop) ----
__global__ void k_prep(int n) {
    int i = blockIdx.x * blockDim.x + threadIdx.x;
    if (i < n) {
        float dis = rsqrtf((float)(g_cnt[i] + 1));  // +1 self loop
        float z = dis * g_y[i];
        g_dis[i] = dis;
        g_z[i]   = z;
        g_acc[i] = z;
    }
}

// ---- kernel 3: acc[col] += z[row]  (1 edge/thread — measured best) ----
__global__ void k_scatter(const void* __restrict__ ei, int e, int n) {
    int i = blockIdx.x * blockDim.x + threadIdx.x;
    if (i >= e) return;
    int is32 = g_is32;
    int r = load_idx(ei, is32, i);
    int c = load_idx(ei, is32, (long long)e + i);
    if ((unsigned)r < (unsigned)n && (unsigned)c < (unsigned)n)
        atomicAdd(&g_acc[c], __ldg(&g_z[r]));
}

// ---- kernel 4: z' = dis^2 * acc; acc = z' (self loop for next hop) ----
__global__ void k_rescale(int n) {
    int i = blockIdx.x * blockDim.x + threadIdx.x;
    if (i < n) {
        float dis = g_dis[i];
        float v = dis * dis * g_acc[i];
        g_z[i]   = v;
        g_acc[i] = v;
    }
}

// ---- kernel 5: out = dis * acc + b ----
__global__ void k_finish(float* __restrict__ out,
                         const float* __restrict__ b, int n) {
    int i = blockIdx.x * blockDim.x + threadIdx.x;
    if (i < n) out[i] = g_dis[i] * g_acc[i] + b[0];
}

extern "C" void kernel_launch(void* const* d_in, const int* in_sizes, int n_in,
                              void* d_out, int out_size) {
    const float* x  = (const float*)d_in[0];
    const void*  ei = d_in[1];                 // [2, E], int32 or int64
    const float* W  = (const float*)d_in[2];
    const float* b  = (const float*)d_in[3];
    float* out = (float*)d_out;

    int n = in_sizes[0] / DFEAT;      // 100000
    int e = in_sizes[1] / 2;          // 600000

    const int T = 256;
    int gbN = (n + T - 1) / T;
    int gbE = (e + T - 1) / T;

    k_init_detect  <<<gbN, T>>>((const int*)ei, e, n);
    k_project_count<<<PC_BLOCKS, PC_T>>>(x, W, ei, n, e);
    k_prep         <<<gbN, T>>>(n);
    k_scatter      <<<gbE, T>>>(ei, e, n);   // hop 1
    k_rescale      <<<gbN, T>>>(n);
    k_scatter      <<<gbE, T>>>(ei, e, n);   // hop 2
    k_finish       <<<gbN, T>>>(out, b, n);
}